// round 15
// baseline (speedup 1.0000x reference)
#include <cuda_runtime.h>
#include <cuda_fp16.h>
#include <math.h>

// Problem constants (fixed by the reference)
#define MM 3
#define BB 65536
#define NN 360
#define MS_ITERS 10
#define KAPPA 10.0f
#define LOG2E 1.4426950408889634f
#define KL2E (KAPPA * LOG2E)

#define WARPS_PER_BLOCK 4
#define THREADS_PER_BLOCK (WARPS_PER_BLOCK * 32)
#define NSLOT 3   // per-lane packed antipodal slots (each = 2+2 bins)

typedef unsigned long long u64;

// Precomputed constant tables (built once per launch by init_tables).
// Antipodal layout: slot m of lane l covers half-bin float2 f = l + 32m,
// i.e. bins (2f, 2f+1); antipodal bins (2f+180, 2f+181) reuse the same
// table entries negated (handled algebraically in the kernel).
__device__ float4 g_tab[96];
__device__ float4 g_mlp[8 * 32];

__global__ void init_tables(const float* __restrict__ W1,
                            const float* __restrict__ b1,
                            const float* __restrict__ W2,
                            const float* __restrict__ b2) {
    int t = threadIdx.x;
    if (t < 96) {
        float c0 = 0.0f, s0 = 0.0f, c1 = 0.0f, s1 = 0.0f;
        if (t < 90) {
            int n0 = 2 * t;
            float th0 = 6.283185307179586f * (float)n0 / (float)NN;
            float th1 = 6.283185307179586f * (float)(n0 + 1) / (float)NN;
            sincosf(th0, &s0, &c0);
            sincosf(th1, &s1, &c1);
        }
        g_tab[t] = make_float4(KL2E * c0, KL2E * c1, KL2E * s0, KL2E * s1);
    } else if (t < 96 + 32) {
        int l = t - 96;
        int j = 4 * l;
#pragma unroll
        for (int r = 0; r < 4; r++)
            g_mlp[r * 32 + l] = make_float4(W1[r * 128 + j], W1[r * 128 + j + 1],
                                            W1[r * 128 + j + 2], W1[r * 128 + j + 3]);
        g_mlp[4 * 32 + l] = make_float4(b1[j], b1[j + 1], b1[j + 2], b1[j + 3]);
        g_mlp[5 * 32 + l] = make_float4(W2[2 * j + 0], W2[2 * j + 1],
                                        W2[2 * j + 2], W2[2 * j + 3]);
        g_mlp[6 * 32 + l] = make_float4(W2[2 * j + 4], W2[2 * j + 5],
                                        W2[2 * j + 6], W2[2 * j + 7]);
        g_mlp[7 * 32 + l] = make_float4(b2[0], b2[1], 0.0f, 0.0f);
    }
}

__device__ __forceinline__ float ex2f(float x) {
    float y;
    asm("ex2.approx.ftz.f32 %0, %1;" : "=f"(y) : "f"(x));
    return y;
}

__device__ __forceinline__ u64 pack2(float lo, float hi) {
    u64 r;
    asm("mov.b64 %0, {%1, %2};" : "=l"(r) : "f"(lo), "f"(hi));
    return r;
}
__device__ __forceinline__ void unpack2(u64 v, float& lo, float& hi) {
    asm("mov.b64 {%0, %1}, %2;" : "=f"(lo), "=f"(hi) : "l"(v));
}
__device__ __forceinline__ u64 fma2(u64 a, u64 b, u64 c) {
    u64 d;
    asm("fma.rn.f32x2 %0, %1, %2, %3;" : "=l"(d) : "l"(a), "l"(b), "l"(c));
    return d;
}
__device__ __forceinline__ u64 mul2(u64 a, u64 b) {
    u64 d;
    asm("mul.rn.f32x2 %0, %1, %2;" : "=l"(d) : "l"(a), "l"(b));
    return d;
}
__device__ __forceinline__ u64 add2(u64 a, u64 b) {
    u64 d;
    asm("add.rn.f32x2 %0, %1, %2;" : "=l"(d) : "l"(a), "l"(b));
    return d;
}
__device__ __forceinline__ u64 sub2(u64 a, u64 b) {
    u64 d;
    asm("sub.rn.f32x2 %0, %1, %2;" : "=l"(d) : "l"(a), "l"(b));
    return d;
}

// scalar warp sum (5 SHFL.32)
__device__ __forceinline__ float warp_sum(float v) {
    v += __shfl_xor_sync(0xFFFFFFFFu, v, 16);
    v += __shfl_xor_sync(0xFFFFFFFFu, v, 8);
    v += __shfl_xor_sync(0xFFFFFFFFu, v, 4);
    v += __shfl_xor_sync(0xFFFFFFFFu, v, 2);
    v += __shfl_xor_sync(0xFFFFFFFFu, v, 1);
    return v;
}

// Parity-interleaved pair reduction (6 SHFL.32 for two sums).
__device__ __forceinline__ void preduce2(float& a, float& b, int lane) {
    const bool odd = lane & 1;
    float z = odd ? b : a;
    float o = odd ? a : b;
    z += __shfl_xor_sync(0xFFFFFFFFu, o, 1);
    z += __shfl_xor_sync(0xFFFFFFFFu, z, 2);
    z += __shfl_xor_sync(0xFFFFFFFFu, z, 4);
    z += __shfl_xor_sync(0xFFFFFFFFu, z, 8);
    z += __shfl_xor_sync(0xFFFFFFFFu, z, 16);
    float other = __shfl_xor_sync(0xFFFFFFFFu, z, 1);
    a = odd ? other : z;
    b = odd ? z : other;
}

// logits float2 -> packed exps via ex2(x*log2e) (f32, softmax precision)
__device__ __forceinline__ u64 conv2(const float2& q) {
    u64 xs = mul2(pack2(q.x, q.y), pack2(LOG2E, LOG2E));
    float a0, a1;
    unpack2(xs, a0, a1);
    return pack2(ex2f(a0), ex2f(a1));
}

// horizontal sum of 6 packed pairs -> scalar
__device__ __forceinline__ float hsum6(const u64* ep, const u64* em) {
    u64 acc = add2(add2(ep[0], em[0]),
                   add2(add2(ep[1], em[1]), add2(ep[2], em[2])));
    float lo, hi;
    unpack2(acc, lo, hi);
    return lo + hi;
}

__global__ void __launch_bounds__(THREADS_PER_BLOCK, 10)
angle_ensemble_kernel(const float* __restrict__ von,      // [M, B, N]
                      const float* __restrict__ sin_vec,  // [B, 2]
                      float* __restrict__ out)            // [B, 2]
{
    const int tid = threadIdx.x;
    const int warp = tid >> 5;
    const int lane = tid & 31;
    const int b = blockIdx.x * WARPS_PER_BLOCK + warp;
    const float* __restrict__ base = von + (size_t)b * NN;

    const float NEG_INF = __int_as_float(0xff800000);
    const float2 NEG_INF2 = make_float2(NEG_INF, NEG_INF);
    const bool v2 = lane < 26;  // slot m=2 validity (f = lane+64 < 90)

    // ---- Mixture of softmaxes (antipodal layout, f32) ----
    u64 wp[NSLOT], wm[NSLOT];
    {
        const float2* r0 = (const float2*)base;
        const float2* r1 = (const float2*)(base + (size_t)BB * NN);
        const float2* r2 = (const float2*)(base + (size_t)2 * BB * NN);

        u64 eap[NSLOT], eam[NSLOT], ebp[NSLOT], ebm[NSLOT];
        eap[0] = conv2(r0[lane]);
        eap[1] = conv2(r0[lane + 32]);
        eap[2] = conv2(v2 ? r0[lane + 64] : NEG_INF2);
        eam[0] = conv2(r0[90 + lane]);
        eam[1] = conv2(r0[90 + lane + 32]);
        eam[2] = conv2(v2 ? r0[90 + lane + 64] : NEG_INF2);
        ebp[0] = conv2(r1[lane]);
        ebp[1] = conv2(r1[lane + 32]);
        ebp[2] = conv2(v2 ? r1[lane + 64] : NEG_INF2);
        ebm[0] = conv2(r1[90 + lane]);
        ebm[1] = conv2(r1[90 + lane + 32]);
        ebm[2] = conv2(v2 ? r1[90 + lane + 64] : NEG_INF2);

        float suma = hsum6(eap, eam);
        float sumb = hsum6(ebp, ebm);
        preduce2(suma, sumb, lane);
        u64 inva2, invb2;
        {
            float ia = __frcp_rn(suma), ib = __frcp_rn(sumb);
            inva2 = pack2(ia, ia);
            invb2 = pack2(ib, ib);
        }
#pragma unroll
        for (int m = 0; m < NSLOT; m++) {
            wp[m] = fma2(ebp[m], invb2, mul2(eap[m], inva2));
            wm[m] = fma2(ebm[m], invb2, mul2(eam[m], inva2));
        }

        eap[0] = conv2(r2[lane]);
        eap[1] = conv2(r2[lane + 32]);
        eap[2] = conv2(v2 ? r2[lane + 64] : NEG_INF2);
        eam[0] = conv2(r2[90 + lane]);
        eam[1] = conv2(r2[90 + lane + 32]);
        eam[2] = conv2(v2 ? r2[90 + lane + 64] : NEG_INF2);
        float sumc = warp_sum(hsum6(eap, eam));
        float ic = __frcp_rn(sumc);
        u64 invc2 = pack2(ic, ic);
#pragma unroll
        for (int m = 0; m < NSLOT; m++) {
            wp[m] = fma2(eap[m], invc2, wp[m]);
            wm[m] = fma2(eam[m], invc2, wm[m]);
        }
    }

    // ---- Load scaled bin table (half-circle); init circular mean ----
    u64 c2[NSLOT], s2[NSLOT];
    u64 C2 = 0ull, S2 = 0ull;
#pragma unroll
    for (int m = 0; m < NSLOT; m++) {
        float4 t = g_tab[lane + 32 * m];   // L2/L1-hot, coalesced
        c2[m] = pack2(t.x, t.y);
        s2[m] = pack2(t.z, t.w);
        u64 d2 = sub2(wp[m], wm[m]);
        C2 = fma2(d2, c2[m], C2);
        S2 = fma2(d2, s2[m], S2);
    }

    float ct, st;
    {
        float x0, x1, y0, y1;
        unpack2(C2, x0, x1);
        unpack2(S2, y0, y1);
        float C = x0 + x1, S = y0 + y1;
        preduce2(C, S, lane);
        float r = rsqrtf(fmaf(S, S, C * C));
        ct = C * r;   // cos(theta)
        st = S * r;   // sin(theta)
    }

    // ---- mean-shift iterations ----
    // Antipodal + dual-half exp: the 4 exps per slot (u0,u1,-u0,-u1) cost
    // TWO ex2.approx.f16x2 MUFU ops instead of four f32 ex2. |u| <= 14.43
    // so 2^u <= 22066 < f16 max; f16 rel err ~5e-4 per bin is random-signed
    // noise across ~20 effective bins -> ~1e-4 direction noise per iter,
    // non-accumulating under contraction. Weights stay f32.
    for (int it = 0; it < MS_ITERS; it++) {
        u64 ct2 = pack2(ct, ct);
        u64 st2 = pack2(st, st);
        u64 Ca = 0ull, Sa = 0ull;
#pragma unroll
        for (int m = 0; m < NSLOT; m++) {
            u64 u = fma2(ct2, c2[m], mul2(st2, s2[m]));
            float u0, u1;
            unpack2(u, u0, u1);
            __half2 hp = __floats2half2_rn(u0, u1);
            __half2 hm = __floats2half2_rn(-u0, -u1);
            __half2 ep = h2exp2(hp);
            __half2 em = h2exp2(hm);
            float2 fp = __half22float2(ep);
            float2 fm = __half22float2(em);
            u64 kp = mul2(wp[m], pack2(fp.x, fp.y));
            u64 km = mul2(wm[m], pack2(fm.x, fm.y));
            u64 kd = sub2(kp, km);
            Ca = fma2(kd, c2[m], Ca);
            Sa = fma2(kd, s2[m], Sa);
        }
        float x0, x1, y0, y1;
        unpack2(Ca, x0, x1);
        unpack2(Sa, y0, y1);
        float Ci = x0 + x1, Si = y0 + y1;
        preduce2(Ci, Si, lane);
        float rr = rsqrtf(fmaf(Si, Si, Ci * Ci));
        float nct = Ci * rr;
        float nst = Si * rr;
        float d = fabsf(nct - ct) + fabsf(nst - st);
        ct = nct;
        st = nst;
        // Warp-uniform early exit (R12-calibrated).
        if (d < 5e-4f) break;
    }

    // ---- tiny MLP head from precomputed per-lane packed params ----
    float2 sv = *(const float2*)(sin_vec + 2 * (size_t)b);

    float4 w1r0 = g_mlp[0 * 32 + lane];
    float4 w1r1 = g_mlp[1 * 32 + lane];
    float4 w1r2 = g_mlp[2 * 32 + lane];
    float4 w1r3 = g_mlp[3 * 32 + lane];
    float4 bb1  = g_mlp[4 * 32 + lane];
    float4 w2a  = g_mlp[5 * 32 + lane];
    float4 w2b  = g_mlp[6 * 32 + lane];
    float4 bb2  = g_mlp[7 * 32 + lane];

    float h0 = fmaf(sv.x, w1r0.x, bb1.x); h0 = fmaf(sv.y, w1r1.x, h0);
    h0 = fmaf(ct, w1r2.x, h0); h0 = fmaf(st, w1r3.x, h0); h0 = fmaxf(h0, 0.0f);
    float h1 = fmaf(sv.x, w1r0.y, bb1.y); h1 = fmaf(sv.y, w1r1.y, h1);
    h1 = fmaf(ct, w1r2.y, h1); h1 = fmaf(st, w1r3.y, h1); h1 = fmaxf(h1, 0.0f);
    float h2 = fmaf(sv.x, w1r0.z, bb1.z); h2 = fmaf(sv.y, w1r1.z, h2);
    h2 = fmaf(ct, w1r2.z, h2); h2 = fmaf(st, w1r3.z, h2); h2 = fmaxf(h2, 0.0f);
    float h3 = fmaf(sv.x, w1r0.w, bb1.w); h3 = fmaf(sv.y, w1r1.w, h3);
    h3 = fmaf(ct, w1r2.w, h3); h3 = fmaxf(fmaf(st, w1r3.w, h3), 0.0f);

    u64 oacc = fma2(pack2(h0, h0), pack2(w2a.x, w2a.y), 0ull);
    oacc = fma2(pack2(h1, h1), pack2(w2a.z, w2a.w), oacc);
    oacc = fma2(pack2(h2, h2), pack2(w2b.x, w2b.y), oacc);
    oacc = fma2(pack2(h3, h3), pack2(w2b.z, w2b.w), oacc);
    float o0, o1;
    unpack2(oacc, o0, o1);
    preduce2(o0, o1, lane);

    if (lane == 0) {
        o0 += bb2.x;
        o1 += bb2.y;
        float nrm = sqrtf(fmaf(o0, o0, o1 * o1));
        nrm = fmaxf(nrm, 1e-12f);
        float inv = 1.0f / nrm;
        *(float2*)(out + 2 * (size_t)b) = make_float2(o0 * inv, o1 * inv);
    }
}

extern "C" void kernel_launch(void* const* d_in, const int* in_sizes, int n_in,
                              void* d_out, int out_size) {
    const float* von     = (const float*)d_in[0];  // [3, 65536, 360]
    const float* sin_vec = (const float*)d_in[1];  // [65536, 2]
    const float* W1      = (const float*)d_in[2];  // [4, 128]
    const float* b1      = (const float*)d_in[3];  // [128]
    const float* W2      = (const float*)d_in[4];  // [128, 2]
    const float* b2      = (const float*)d_in[5];  // [2]
    float* out = (float*)d_out;                    // [65536, 2]

    init_tables<<<1, 96 + 32>>>(W1, b1, W2, b2);
    const int blocks = BB / WARPS_PER_BLOCK;  // 16384
    angle_ensemble_kernel<<<blocks, THREADS_PER_BLOCK>>>(von, sin_vec, out);
}

// round 16
// speedup vs baseline: 1.3803x; 1.3803x over previous
#include <cuda_runtime.h>
#include <math.h>

// Problem constants (fixed by the reference)
#define MM 3
#define BB 65536
#define NN 360
#define MS_ITERS 10
#define KAPPA 10.0f
#define LOG2E 1.4426950408889634f
#define KL2E (KAPPA * LOG2E)

#define WARPS_PER_BLOCK 4
#define THREADS_PER_BLOCK (WARPS_PER_BLOCK * 32)
#define NSLOT 3   // per-lane packed antipodal slots (each = 2+2 bins)

typedef unsigned long long u64;

// Precomputed constant tables (built once per launch by init_tables).
// Antipodal layout: slot m of lane l covers half-bin float2 f = l + 32m,
// i.e. bins (2f, 2f+1); antipodal bins (2f+180, 2f+181) reuse the same
// table entries negated (handled algebraically in the kernel).
__device__ float4 g_tab[96];
__device__ float4 g_mlp[8 * 32];

__global__ void init_tables(const float* __restrict__ W1,
                            const float* __restrict__ b1,
                            const float* __restrict__ W2,
                            const float* __restrict__ b2) {
    int t = threadIdx.x;
    if (t < 96) {
        float c0 = 0.0f, s0 = 0.0f, c1 = 0.0f, s1 = 0.0f;
        if (t < 90) {
            int n0 = 2 * t;
            float th0 = 6.283185307179586f * (float)n0 / (float)NN;
            float th1 = 6.283185307179586f * (float)(n0 + 1) / (float)NN;
            sincosf(th0, &s0, &c0);
            sincosf(th1, &s1, &c1);
        }
        g_tab[t] = make_float4(KL2E * c0, KL2E * c1, KL2E * s0, KL2E * s1);
    } else if (t < 96 + 32) {
        int l = t - 96;
        int j = 4 * l;
#pragma unroll
        for (int r = 0; r < 4; r++)
            g_mlp[r * 32 + l] = make_float4(W1[r * 128 + j], W1[r * 128 + j + 1],
                                            W1[r * 128 + j + 2], W1[r * 128 + j + 3]);
        g_mlp[4 * 32 + l] = make_float4(b1[j], b1[j + 1], b1[j + 2], b1[j + 3]);
        g_mlp[5 * 32 + l] = make_float4(W2[2 * j + 0], W2[2 * j + 1],
                                        W2[2 * j + 2], W2[2 * j + 3]);
        g_mlp[6 * 32 + l] = make_float4(W2[2 * j + 4], W2[2 * j + 5],
                                        W2[2 * j + 6], W2[2 * j + 7]);
        g_mlp[7 * 32 + l] = make_float4(b2[0], b2[1], 0.0f, 0.0f);
    }
}

__device__ __forceinline__ float ex2f(float x) {
    float y;
    asm("ex2.approx.ftz.f32 %0, %1;" : "=f"(y) : "f"(x));
    return y;
}

__device__ __forceinline__ u64 pack2(float lo, float hi) {
    u64 r;
    asm("mov.b64 %0, {%1, %2};" : "=l"(r) : "f"(lo), "f"(hi));
    return r;
}
__device__ __forceinline__ void unpack2(u64 v, float& lo, float& hi) {
    asm("mov.b64 {%0, %1}, %2;" : "=f"(lo), "=f"(hi) : "l"(v));
}
__device__ __forceinline__ u64 fma2(u64 a, u64 b, u64 c) {
    u64 d;
    asm("fma.rn.f32x2 %0, %1, %2, %3;" : "=l"(d) : "l"(a), "l"(b), "l"(c));
    return d;
}
__device__ __forceinline__ u64 mul2(u64 a, u64 b) {
    u64 d;
    asm("mul.rn.f32x2 %0, %1, %2;" : "=l"(d) : "l"(a), "l"(b));
    return d;
}
__device__ __forceinline__ u64 add2(u64 a, u64 b) {
    u64 d;
    asm("add.rn.f32x2 %0, %1, %2;" : "=l"(d) : "l"(a), "l"(b));
    return d;
}
__device__ __forceinline__ u64 sub2(u64 a, u64 b) {
    u64 d;
    asm("sub.rn.f32x2 %0, %1, %2;" : "=l"(d) : "l"(a), "l"(b));
    return d;
}

// scalar warp sum (5 SHFL.32)
__device__ __forceinline__ float warp_sum(float v) {
    v += __shfl_xor_sync(0xFFFFFFFFu, v, 16);
    v += __shfl_xor_sync(0xFFFFFFFFu, v, 8);
    v += __shfl_xor_sync(0xFFFFFFFFu, v, 4);
    v += __shfl_xor_sync(0xFFFFFFFFu, v, 2);
    v += __shfl_xor_sync(0xFFFFFFFFu, v, 1);
    return v;
}

// Parity-interleaved pair reduction (6 SHFL.32 for two sums).
__device__ __forceinline__ void preduce2(float& a, float& b, int lane) {
    const bool odd = lane & 1;
    float z = odd ? b : a;
    float o = odd ? a : b;
    z += __shfl_xor_sync(0xFFFFFFFFu, o, 1);
    z += __shfl_xor_sync(0xFFFFFFFFu, z, 2);
    z += __shfl_xor_sync(0xFFFFFFFFu, z, 4);
    z += __shfl_xor_sync(0xFFFFFFFFu, z, 8);
    z += __shfl_xor_sync(0xFFFFFFFFu, z, 16);
    float other = __shfl_xor_sync(0xFFFFFFFFu, z, 1);
    a = odd ? other : z;
    b = odd ? z : other;
}

// logits float2 -> packed exps via ex2(x*log2e)
__device__ __forceinline__ u64 conv2(const float2& q) {
    u64 xs = mul2(pack2(q.x, q.y), pack2(LOG2E, LOG2E));
    float a0, a1;
    unpack2(xs, a0, a1);
    return pack2(ex2f(a0), ex2f(a1));
}

// horizontal sum of 6 packed pairs -> scalar
__device__ __forceinline__ float hsum6(const u64* ep, const u64* em) {
    u64 acc = add2(add2(ep[0], em[0]),
                   add2(add2(ep[1], em[1]), add2(ep[2], em[2])));
    float lo, hi;
    unpack2(acc, lo, hi);
    return lo + hi;
}

__global__ void __launch_bounds__(THREADS_PER_BLOCK, 12)
angle_ensemble_kernel(const float* __restrict__ von,      // [M, B, N]
                      const float* __restrict__ sin_vec,  // [B, 2]
                      float* __restrict__ out)            // [B, 2]
{
    const int tid = threadIdx.x;
    const int warp = tid >> 5;
    const int lane = tid & 31;
    const int b = blockIdx.x * WARPS_PER_BLOCK + warp;
    const float* __restrict__ base = von + (size_t)b * NN;

    const float NEG_INF = __int_as_float(0xff800000);
    const float2 NEG_INF2 = make_float2(NEG_INF, NEG_INF);
    const bool v2 = lane < 26;  // slot m=2 validity (f = lane+64 < 90)

    // ---- Mixture of softmaxes (antipodal layout) ----
    // wp[m] = mixture weights of bins (2f, 2f+1); wm[m] = antipodal bins.
    // Invalid slots load -inf -> exp 0 -> weight 0 everywhere downstream.
    u64 wp[NSLOT], wm[NSLOT];
    {
        const float2* r0 = (const float2*)base;
        const float2* r1 = (const float2*)(base + (size_t)BB * NN);
        const float2* r2 = (const float2*)(base + (size_t)2 * BB * NN);

        u64 eap[NSLOT], eam[NSLOT], ebp[NSLOT], ebm[NSLOT];
        // rows a, b
        eap[0] = conv2(r0[lane]);
        eap[1] = conv2(r0[lane + 32]);
        eap[2] = conv2(v2 ? r0[lane + 64] : NEG_INF2);
        eam[0] = conv2(r0[90 + lane]);
        eam[1] = conv2(r0[90 + lane + 32]);
        eam[2] = conv2(v2 ? r0[90 + lane + 64] : NEG_INF2);
        ebp[0] = conv2(r1[lane]);
        ebp[1] = conv2(r1[lane + 32]);
        ebp[2] = conv2(v2 ? r1[lane + 64] : NEG_INF2);
        ebm[0] = conv2(r1[90 + lane]);
        ebm[1] = conv2(r1[90 + lane + 32]);
        ebm[2] = conv2(v2 ? r1[90 + lane + 64] : NEG_INF2);

        float suma = hsum6(eap, eam);
        float sumb = hsum6(ebp, ebm);
        preduce2(suma, sumb, lane);
        u64 inva2, invb2;
        {
            float ia = __frcp_rn(suma), ib = __frcp_rn(sumb);
            inva2 = pack2(ia, ia);
            invb2 = pack2(ib, ib);
        }
#pragma unroll
        for (int m = 0; m < NSLOT; m++) {
            wp[m] = fma2(ebp[m], invb2, mul2(eap[m], inva2));
            wm[m] = fma2(ebm[m], invb2, mul2(eam[m], inva2));
        }

        // row c (reuse ea registers)
        eap[0] = conv2(r2[lane]);
        eap[1] = conv2(r2[lane + 32]);
        eap[2] = conv2(v2 ? r2[lane + 64] : NEG_INF2);
        eam[0] = conv2(r2[90 + lane]);
        eam[1] = conv2(r2[90 + lane + 32]);
        eam[2] = conv2(v2 ? r2[90 + lane + 64] : NEG_INF2);
        float sumc = warp_sum(hsum6(eap, eam));
        float ic = __frcp_rn(sumc);
        u64 invc2 = pack2(ic, ic);
#pragma unroll
        for (int m = 0; m < NSLOT; m++) {
            wp[m] = fma2(eap[m], invc2, wp[m]);
            wm[m] = fma2(eam[m], invc2, wm[m]);
        }
    }

    // ---- Load scaled bin table (half-circle only); init circular mean ----
    // Antipodal contribution: (w+ - w-) * (c, s).
    u64 c2[NSLOT], s2[NSLOT];
    u64 C2 = 0ull, S2 = 0ull;
#pragma unroll
    for (int m = 0; m < NSLOT; m++) {
        float4 t = g_tab[lane + 32 * m];   // L2/L1-hot, coalesced
        c2[m] = pack2(t.x, t.y);
        s2[m] = pack2(t.z, t.w);
        u64 d2 = sub2(wp[m], wm[m]);
        C2 = fma2(d2, c2[m], C2);
        S2 = fma2(d2, s2[m], S2);
    }

    float ct, st;
    {
        float x0, x1, y0, y1;
        unpack2(C2, x0, x1);
        unpack2(S2, y0, y1);
        float C = x0 + x1, S = y0 + y1;
        preduce2(C, S, lane);
        float r = rsqrtf(fmaf(S, S, C * C));
        ct = C * r;   // cos(theta)
        st = S * r;   // sin(theta)
    }

    // ---- mean-shift iterations (antipodal: one dot product per 2 bins) ----
    // u = ct*c + st*s; bins at u get w+*ex2(u), antipodal bins w-*ex2(-u);
    // resultant += (k+ - k-) * (c, s).
    for (int it = 0; it < MS_ITERS; it++) {
        u64 ct2 = pack2(ct, ct);
        u64 st2 = pack2(st, st);
        u64 Ca = 0ull, Sa = 0ull;
#pragma unroll
        for (int m = 0; m < NSLOT; m++) {
            u64 u = fma2(ct2, c2[m], mul2(st2, s2[m]));
            float u0, u1;
            unpack2(u, u0, u1);
            u64 kp = mul2(wp[m], pack2(ex2f(u0), ex2f(u1)));
            u64 km = mul2(wm[m], pack2(ex2f(-u0), ex2f(-u1)));
            u64 kd = sub2(kp, km);
            Ca = fma2(kd, c2[m], Ca);
            Sa = fma2(kd, s2[m], Sa);
        }
        float x0, x1, y0, y1;
        unpack2(Ca, x0, x1);
        unpack2(Sa, y0, y1);
        float Ci = x0 + x1, Si = y0 + y1;
        preduce2(Ci, Si, lane);
        float rr = rsqrtf(fmaf(Si, Si, Ci * Ci));
        float nct = Ci * rr;
        float nst = Si * rr;
        float d = fabsf(nct - ct) + fabsf(nst - st);
        ct = nct;
        st = nst;
        // Warp-uniform early exit (R12-calibrated): remaining reference
        // iterations move the output well under the 1e-3 tolerance.
        if (d < 5e-4f) break;
    }

    // ---- tiny MLP head from precomputed per-lane packed params ----
    float2 sv = *(const float2*)(sin_vec + 2 * (size_t)b);

    float4 w1r0 = g_mlp[0 * 32 + lane];
    float4 w1r1 = g_mlp[1 * 32 + lane];
    float4 w1r2 = g_mlp[2 * 32 + lane];
    float4 w1r3 = g_mlp[3 * 32 + lane];
    float4 bb1  = g_mlp[4 * 32 + lane];

    float h0 = fmaf(sv.x, w1r0.x, bb1.x); h0 = fmaf(sv.y, w1r1.x, h0);
    h0 = fmaf(ct, w1r2.x, h0); h0 = fmaf(st, w1r3.x, h0); h0 = fmaxf(h0, 0.0f);
    float h1 = fmaf(sv.x, w1r0.y, bb1.y); h1 = fmaf(sv.y, w1r1.y, h1);
    h1 = fmaf(ct, w1r2.y, h1); h1 = fmaf(st, w1r3.y, h1); h1 = fmaxf(h1, 0.0f);
    float h2 = fmaf(sv.x, w1r0.z, bb1.z); h2 = fmaf(sv.y, w1r1.z, h2);
    h2 = fmaf(ct, w1r2.z, h2); h2 = fmaf(st, w1r3.z, h2); h2 = fmaxf(h2, 0.0f);
    float h3 = fmaf(sv.x, w1r0.w, bb1.w); h3 = fmaf(sv.y, w1r1.w, h3);
    h3 = fmaf(ct, w1r2.w, h3); h3 = fmaxf(fmaf(st, w1r3.w, h3), 0.0f);

    float4 w2a  = g_mlp[5 * 32 + lane];
    float4 w2b  = g_mlp[6 * 32 + lane];
    float4 bb2  = g_mlp[7 * 32 + lane];

    u64 oacc = fma2(pack2(h0, h0), pack2(w2a.x, w2a.y), 0ull);
    oacc = fma2(pack2(h1, h1), pack2(w2a.z, w2a.w), oacc);
    oacc = fma2(pack2(h2, h2), pack2(w2b.x, w2b.y), oacc);
    oacc = fma2(pack2(h3, h3), pack2(w2b.z, w2b.w), oacc);
    float o0, o1;
    unpack2(oacc, o0, o1);
    preduce2(o0, o1, lane);

    if (lane == 0) {
        o0 += bb2.x;
        o1 += bb2.y;
        float nrm = sqrtf(fmaf(o0, o0, o1 * o1));
        nrm = fmaxf(nrm, 1e-12f);
        float inv = 1.0f / nrm;
        *(float2*)(out + 2 * (size_t)b) = make_float2(o0 * inv, o1 * inv);
    }
}

extern "C" void kernel_launch(void* const* d_in, const int* in_sizes, int n_in,
                              void* d_out, int out_size) {
    const float* von     = (const float*)d_in[0];  // [3, 65536, 360]
    const float* sin_vec = (const float*)d_in[1];  // [65536, 2]
    const float* W1      = (const float*)d_in[2];  // [4, 128]
    const float* b1      = (const float*)d_in[3];  // [128]
    const float* W2      = (const float*)d_in[4];  // [128, 2]
    const float* b2      = (const float*)d_in[5];  // [2]
    float* out = (float*)d_out;                    // [65536, 2]

    init_tables<<<1, 96 + 32>>>(W1, b1, W2, b2);
    const int blocks = BB / WARPS_PER_BLOCK;  // 16384
    angle_ensemble_kernel<<<blocks, THREADS_PER_BLOCK>>>(von, sin_vec, out);
}